// round 2
// baseline (speedup 1.0000x reference)
#include <cuda_runtime.h>
#include <cstdint>

#define B_ 4
#define H_ 8
#define N_ 2048
#define D_ 64
#define KC_ 512          // H_*D_
#define KTOP 16
#define SCALE (1.0f/64.0f)   // (1/sqrt(D)) * (1/H)

// 64 MB scratch for z = logits + gumbel  (allocation-free rule: __device__ global)
__device__ float g_z[(size_t)B_ * N_ * N_];

// ---------------------------------------------------------------------------
// Kernel 1: per-batch SGEMM  z[n,m] = SCALE * sum_c Qc[n,c]*Kc[m,c] + gumbel(u)
// 128x128 tile, BK=8, 256 threads, 8x8 microtile per thread.
// ---------------------------------------------------------------------------
__global__ __launch_bounds__(256) void gemm_gumbel_kernel(
    const float* __restrict__ q,
    const float* __restrict__ k,
    const float* __restrict__ u)
{
    const int b  = blockIdx.z;
    const int m0 = blockIdx.x * 128;   // K-rows (columns of output)
    const int n0 = blockIdx.y * 128;   // Q-rows

    __shared__ float As[8][128];
    __shared__ float Bs[8][128];

    const int tid = threadIdx.x;
    const int lr  = tid >> 1;          // 0..127: row within tile for loading
    const int lc4 = (tid & 1) * 4;     // 0 or 4: starting col of float4

    const size_t bbase = (size_t)b * H_ * N_ * D_;

    const int tn = (tid >> 4) * 8;     // 0..120 row offset of microtile
    const int tm = (tid & 15) * 8;     // 0..120 col offset of microtile

    float acc[8][8];
#pragma unroll
    for (int i = 0; i < 8; i++)
#pragma unroll
        for (int j = 0; j < 8; j++) acc[i][j] = 0.0f;

#pragma unroll 1
    for (int c0 = 0; c0 < KC_; c0 += 8) {
        const int h  = c0 >> 6;
        const int dd = (c0 & 63) + lc4;
        const size_t hoff = bbase + (size_t)h * (N_ * D_);

        const float4 av = *(const float4*)(q + hoff + (size_t)(n0 + lr) * D_ + dd);
        const float4 bv = *(const float4*)(k + hoff + (size_t)(m0 + lr) * D_ + dd);

        __syncthreads();
        As[lc4 + 0][lr] = av.x;  As[lc4 + 1][lr] = av.y;
        As[lc4 + 2][lr] = av.z;  As[lc4 + 3][lr] = av.w;
        Bs[lc4 + 0][lr] = bv.x;  Bs[lc4 + 1][lr] = bv.y;
        Bs[lc4 + 2][lr] = bv.z;  Bs[lc4 + 3][lr] = bv.w;
        __syncthreads();

#pragma unroll
        for (int kk = 0; kk < 8; kk++) {
            float a[8], bb[8];
            *(float4*)(a)      = *(const float4*)(&As[kk][tn]);
            *(float4*)(a + 4)  = *(const float4*)(&As[kk][tn + 4]);
            *(float4*)(bb)     = *(const float4*)(&Bs[kk][tm]);
            *(float4*)(bb + 4) = *(const float4*)(&Bs[kk][tm + 4]);
#pragma unroll
            for (int i = 0; i < 8; i++)
#pragma unroll
                for (int j = 0; j < 8; j++)
                    acc[i][j] = fmaf(a[i], bb[j], acc[i][j]);
        }
    }

    // Epilogue: z = acc*SCALE + gumbel(u);  softmax skipped (monotonic).
    const size_t ubase = (size_t)b * N_ * N_;
#pragma unroll
    for (int i = 0; i < 8; i++) {
        const int n = n0 + tn + i;
        const float* urow = u + ubase + (size_t)n * N_ + (m0 + tm);
        float*       zrow = g_z + ubase + (size_t)n * N_ + (m0 + tm);
#pragma unroll
        for (int j4 = 0; j4 < 8; j4 += 4) {
            float4 uv = *(const float4*)(urow + j4);
            float4 zv;
            zv.x = acc[i][j4 + 0] * SCALE + (-logf(-logf(uv.x + 1e-9f) + 1e-9f));
            zv.y = acc[i][j4 + 1] * SCALE + (-logf(-logf(uv.y + 1e-9f) + 1e-9f));
            zv.z = acc[i][j4 + 2] * SCALE + (-logf(-logf(uv.z + 1e-9f) + 1e-9f));
            zv.w = acc[i][j4 + 3] * SCALE + (-logf(-logf(uv.w + 1e-9f) + 1e-9f));
            *(float4*)(zrow + j4) = zv;
        }
    }
}

// ---------------------------------------------------------------------------
// Kernel 2: exact per-row 16th-largest via radix select on order-preserving
// uint keys, then write binary mask (>= threshold, ties included like the ref).
// One block (256 threads) per row of 2048.
// ---------------------------------------------------------------------------
__device__ __forceinline__ uint32_t f2ord(float f) {
    uint32_t v = __float_as_uint(f);
    return (v & 0x80000000u) ? ~v : (v | 0x80000000u);
}

__global__ __launch_bounds__(256) void topk_mask_kernel(float* __restrict__ out)
{
    const int row = blockIdx.x;                 // 0 .. B_*N_-1
    const float* z = g_z + (size_t)row * N_;

    __shared__ uint32_t keys[N_];
    __shared__ int      hist[256];
    __shared__ uint32_t s_prefix;
    __shared__ int      s_k;

    const int tid = threadIdx.x;

    for (int i = tid; i < N_; i += 256)
        keys[i] = f2ord(z[i]);

    if (tid == 0) { s_prefix = 0u; s_k = KTOP; }
    __syncthreads();

#pragma unroll
    for (int shift = 24; shift >= 0; shift -= 8) {
        hist[tid & 255] = 0;                    // 256 threads -> each zeroes one bin
        __syncthreads();

        const uint32_t pref  = s_prefix;
        const int      kneed = s_k;
        const uint32_t hmask = (shift == 24) ? 0u : (0xFFFFFFFFu << (shift + 8));

        for (int i = tid; i < N_; i += 256) {
            const uint32_t key = keys[i];
            if ((key & hmask) == pref)
                atomicAdd(&hist[(key >> shift) & 255], 1);
        }
        __syncthreads();

        if (tid == 0) {
            int cum = 0;
            for (int bin = 255; bin >= 0; bin--) {
                cum += hist[bin];
                if (cum >= kneed) {
                    s_prefix = pref | ((uint32_t)bin << shift);
                    s_k      = kneed - (cum - hist[bin]);
                    break;
                }
            }
        }
        __syncthreads();
    }

    const uint32_t thresh = s_prefix;           // exact 16th-largest key
    float* o = out + (size_t)row * N_;
    for (int i = tid; i < N_; i += 256)
        o[i] = (keys[i] >= thresh) ? 1.0f : 0.0f;
}

// ---------------------------------------------------------------------------
extern "C" void kernel_launch(void* const* d_in, const int* in_sizes, int n_in,
                              void* d_out, int out_size)
{
    const float* q = (const float*)d_in[0];
    const float* k = (const float*)d_in[1];
    const float* u = (const float*)d_in[2];
    float* out = (float*)d_out;

    dim3 grid(N_ / 128, N_ / 128, B_);          // 16 x 16 x 4
    gemm_gumbel_kernel<<<grid, 256>>>(q, k, u);
    topk_mask_kernel<<<B_ * N_, 256>>>(out);
}